// round 1
// baseline (speedup 1.0000x reference)
#include <cuda_runtime.h>
#include <math.h>

// Problem constants (fixed by the dataset)
#define TOK   8192          // B*S tokens
#define DIM   1024          // model dim D
#define HID   2048          // hidden dim H
#define NE    8             // experts
#define NPAIR (TOK * 2)     // total (token, expert) pairs with top-2

// ---------------------------------------------------------------------------
// Device scratch (static __device__ arrays — no runtime allocation)
// ---------------------------------------------------------------------------
__device__ int   g_counts[NE];
__device__ int   g_offs[NE];
__device__ int   g_ptoken[NE * TOK];   // per-expert token lists (slot-ordered)
__device__ float g_pgate [NE * TOK];
__device__ int   g_ctoken[NPAIR];      // compacted pair -> token
__device__ float g_cgate [NPAIR];      // compacted pair -> gate
__device__ float g_Xg[(size_t)NPAIR * DIM];   // gathered activations  (64 MiB)
__device__ float g_G [(size_t)NPAIR * HID];   // SwiGLU intermediate  (128 MiB)

// ---------------------------------------------------------------------------
// Stage 0: zero expert counters
// ---------------------------------------------------------------------------
__global__ void zero_counts_kernel() {
    if (threadIdx.x < NE) g_counts[threadIdx.x] = 0;
}

// ---------------------------------------------------------------------------
// Stage 1: router — noisy top-2 gating, one warp per token
// ---------------------------------------------------------------------------
__global__ void router_kernel(const float* __restrict__ x,
                              const float* __restrict__ noise,
                              const float* __restrict__ rw,
                              const float* __restrict__ rb,
                              const float* __restrict__ nw,
                              const float* __restrict__ nb)
{
    int gwarp = (int)((blockIdx.x * blockDim.x + threadIdx.x) >> 5);
    int lane  = threadIdx.x & 31;
    if (gwarp >= TOK) return;

    const float* xr = x + (size_t)gwarp * DIM;

    float accR[NE], accN[NE];
#pragma unroll
    for (int e = 0; e < NE; e++) { accR[e] = 0.0f; accN[e] = 0.0f; }

    for (int i = lane; i < DIM; i += 32) {
        float xv = xr[i];
#pragma unroll
        for (int e = 0; e < NE; e++) {
            accR[e] = fmaf(xv, rw[e * DIM + i], accR[e]);
            accN[e] = fmaf(xv, nw[e * DIM + i], accN[e]);
        }
    }
#pragma unroll
    for (int e = 0; e < NE; e++) {
#pragma unroll
        for (int o = 16; o > 0; o >>= 1) {
            accR[e] += __shfl_xor_sync(0xffffffffu, accR[e], o);
            accN[e] += __shfl_xor_sync(0xffffffffu, accN[e], o);
        }
    }

    if (lane == 0) {
        float noisy[NE];
#pragma unroll
        for (int e = 0; e < NE; e++) {
            float lg = accR[e] + rb[e];
            float nl = accN[e] + nb[e];
            // softplus(nl) = max(nl,0) + log1p(exp(-|nl|))  (stable, matches jax)
            float sp = fmaxf(nl, 0.0f) + log1pf(expf(-fabsf(nl)));
            noisy[e] = lg + noise[(size_t)gwarp * NE + e] * sp;
        }
        // top-2 with lowest-index tie-break (strict >)
        int i1 = 0;
#pragma unroll
        for (int e = 1; e < NE; e++) if (noisy[e] > noisy[i1]) i1 = e;
        int i2 = (i1 == 0) ? 1 : 0;
#pragma unroll
        for (int e = 0; e < NE; e++) {
            if (e == i1 || e == i2) continue;
            if (noisy[e] > noisy[i2]) i2 = e;
        }
        // softmax over the two selected values (others are -inf -> gate 0)
        float mx = noisy[i1];
        float e1 = 1.0f;                      // exp(0)
        float e2 = expf(noisy[i2] - mx);
        float inv = 1.0f / (e1 + e2);
        float gte1 = e1 * inv;
        float gte2 = e2 * inv;

        int s1 = atomicAdd(&g_counts[i1], 1);
        g_ptoken[i1 * TOK + s1] = gwarp;
        g_pgate [i1 * TOK + s1] = gte1;
        int s2 = atomicAdd(&g_counts[i2], 1);
        g_ptoken[i2 * TOK + s2] = gwarp;
        g_pgate [i2 * TOK + s2] = gte2;
    }
}

// ---------------------------------------------------------------------------
// Stage 2: tiny prefix scan over 8 counters
// ---------------------------------------------------------------------------
__global__ void scan_offsets_kernel() {
    if (threadIdx.x == 0) {
        int s = 0;
#pragma unroll
        for (int e = 0; e < NE; e++) { g_offs[e] = s; s += g_counts[e]; }
    }
}

// ---------------------------------------------------------------------------
// Stage 3: gather token rows into compact per-expert layout
// one block per (expert, slot); 256 threads copy one 1024-float row via float4
// ---------------------------------------------------------------------------
__global__ void gather_kernel(const float* __restrict__ x) {
    int e    = blockIdx.x >> 13;          // TOK = 2^13
    int slot = blockIdx.x & (TOK - 1);
    if (slot >= g_counts[e]) return;
    int token = g_ptoken[e * TOK + slot];
    int p     = g_offs[e] + slot;

    const float4* src = (const float4*)(x + (size_t)token * DIM);
    float4*       dst = (float4*)(g_Xg + (size_t)p * DIM);
    dst[threadIdx.x] = src[threadIdx.x];  // 256 * 4 = 1024 floats

    if (threadIdx.x == 0) {
        g_ctoken[p] = token;
        g_cgate [p] = g_pgate[e * TOK + slot];
    }
}

// ---------------------------------------------------------------------------
// GEMM tiling
// ---------------------------------------------------------------------------
#define BM 64
#define BN 64
#define BK 16
#define SM_PAD 4

// Stage 4: GEMM1 fused — G = silu(Xg @ w1^T) * (Xg @ w3^T), per expert
__global__ __launch_bounds__(256) void gemm1_kernel(const float* __restrict__ w1,
                                                    const float* __restrict__ w3)
{
    int e   = blockIdx.z;
    int cnt = g_counts[e];
    int m0  = blockIdx.y * BM;
    if (m0 >= cnt) return;
    int base = g_offs[e];
    int n0   = blockIdx.x * BN;

    const float* W1 = w1 + (size_t)e * HID * DIM;
    const float* W3 = w3 + (size_t)e * HID * DIM;

    __shared__ float As [BK][BM + SM_PAD];
    __shared__ float B1s[BK][BN + SM_PAD];
    __shared__ float B3s[BK][BN + SM_PAD];

    int tid = threadIdx.x;
    int lm  = tid >> 2;            // 0..63 : row within tile
    int lk  = (tid & 3) << 2;      // 0,4,8,12 : k offset (float4)
    int ty  = tid >> 4;            // 0..15
    int tx  = tid & 15;            // 0..15

    float acc1[4][4], acc3[4][4];
#pragma unroll
    for (int i = 0; i < 4; i++)
#pragma unroll
        for (int j = 0; j < 4; j++) { acc1[i][j] = 0.0f; acc3[i][j] = 0.0f; }

    bool avalid = (m0 + lm) < cnt;
    const float* Arow  = g_Xg + (size_t)(base + m0 + lm) * DIM;
    const float* B1row = W1 + (size_t)(n0 + lm) * DIM;
    const float* B3row = W3 + (size_t)(n0 + lm) * DIM;

    for (int k0 = 0; k0 < DIM; k0 += BK) {
        float4 a4 = avalid ? *(const float4*)(Arow + k0 + lk)
                           : make_float4(0.f, 0.f, 0.f, 0.f);
        float4 b1 = *(const float4*)(B1row + k0 + lk);
        float4 b3 = *(const float4*)(B3row + k0 + lk);

        As [lk + 0][lm] = a4.x; As [lk + 1][lm] = a4.y;
        As [lk + 2][lm] = a4.z; As [lk + 3][lm] = a4.w;
        B1s[lk + 0][lm] = b1.x; B1s[lk + 1][lm] = b1.y;
        B1s[lk + 2][lm] = b1.z; B1s[lk + 3][lm] = b1.w;
        B3s[lk + 0][lm] = b3.x; B3s[lk + 1][lm] = b3.y;
        B3s[lk + 2][lm] = b3.z; B3s[lk + 3][lm] = b3.w;
        __syncthreads();

#pragma unroll
        for (int kk = 0; kk < BK; kk++) {
            float4 av  = *(const float4*)&As [kk][ty << 2];
            float4 b1v = *(const float4*)&B1s[kk][tx << 2];
            float4 b3v = *(const float4*)&B3s[kk][tx << 2];
            float a[4]  = {av.x,  av.y,  av.z,  av.w};
            float b1a[4] = {b1v.x, b1v.y, b1v.z, b1v.w};
            float b3a[4] = {b3v.x, b3v.y, b3v.z, b3v.w};
#pragma unroll
            for (int i = 0; i < 4; i++)
#pragma unroll
                for (int j = 0; j < 4; j++) {
                    acc1[i][j] = fmaf(a[i], b1a[j], acc1[i][j]);
                    acc3[i][j] = fmaf(a[i], b3a[j], acc3[i][j]);
                }
        }
        __syncthreads();
    }

#pragma unroll
    for (int i = 0; i < 4; i++) {
        int m = m0 + (ty << 2) + i;
        if (m >= cnt) continue;
        float4 o;
        float h;
        h = acc1[i][0]; o.x = h * (1.0f / (1.0f + expf(-h))) * acc3[i][0];
        h = acc1[i][1]; o.y = h * (1.0f / (1.0f + expf(-h))) * acc3[i][1];
        h = acc1[i][2]; o.z = h * (1.0f / (1.0f + expf(-h))) * acc3[i][2];
        h = acc1[i][3]; o.w = h * (1.0f / (1.0f + expf(-h))) * acc3[i][3];
        *(float4*)&g_G[(size_t)(base + m) * HID + n0 + (tx << 2)] = o;
    }
}

// Stage 5: GEMM2 — out[token] += gate * (G @ w2^T), per expert, atomic scatter
__global__ __launch_bounds__(256) void gemm2_kernel(const float* __restrict__ w2,
                                                    float* __restrict__ out)
{
    int e   = blockIdx.z;
    int cnt = g_counts[e];
    int m0  = blockIdx.y * BM;
    if (m0 >= cnt) return;
    int base = g_offs[e];
    int n0   = blockIdx.x * BN;     // over DIM

    const float* W2 = w2 + (size_t)e * DIM * HID;

    __shared__ float As[BK][BM + SM_PAD];
    __shared__ float Bs[BK][BN + SM_PAD];

    int tid = threadIdx.x;
    int lm  = tid >> 2;
    int lk  = (tid & 3) << 2;
    int ty  = tid >> 4;
    int tx  = tid & 15;

    float acc[4][4];
#pragma unroll
    for (int i = 0; i < 4; i++)
#pragma unroll
        for (int j = 0; j < 4; j++) acc[i][j] = 0.0f;

    bool avalid = (m0 + lm) < cnt;
    const float* Arow = g_G + (size_t)(base + m0 + lm) * HID;
    const float* Brow = W2 + (size_t)(n0 + lm) * HID;

    for (int k0 = 0; k0 < HID; k0 += BK) {
        float4 a4 = avalid ? *(const float4*)(Arow + k0 + lk)
                           : make_float4(0.f, 0.f, 0.f, 0.f);
        float4 b4 = *(const float4*)(Brow + k0 + lk);

        As[lk + 0][lm] = a4.x; As[lk + 1][lm] = a4.y;
        As[lk + 2][lm] = a4.z; As[lk + 3][lm] = a4.w;
        Bs[lk + 0][lm] = b4.x; Bs[lk + 1][lm] = b4.y;
        Bs[lk + 2][lm] = b4.z; Bs[lk + 3][lm] = b4.w;
        __syncthreads();

#pragma unroll
        for (int kk = 0; kk < BK; kk++) {
            float4 av = *(const float4*)&As[kk][ty << 2];
            float4 bv = *(const float4*)&Bs[kk][tx << 2];
            float a[4] = {av.x, av.y, av.z, av.w};
            float b[4] = {bv.x, bv.y, bv.z, bv.w};
#pragma unroll
            for (int i = 0; i < 4; i++)
#pragma unroll
                for (int j = 0; j < 4; j++)
                    acc[i][j] = fmaf(a[i], b[j], acc[i][j]);
        }
        __syncthreads();
    }

#pragma unroll
    for (int i = 0; i < 4; i++) {
        int m = m0 + (ty << 2) + i;
        if (m >= cnt) continue;
        int   token = g_ctoken[base + m];
        float gate  = g_cgate [base + m];
        float* orow = out + (size_t)token * DIM + n0 + (tx << 2);
#pragma unroll
        for (int j = 0; j < 4; j++)
            atomicAdd(&orow[j], gate * acc[i][j]);
    }
}

// ---------------------------------------------------------------------------
// Launch
// ---------------------------------------------------------------------------
extern "C" void kernel_launch(void* const* d_in, const int* in_sizes, int n_in,
                              void* d_out, int out_size)
{
    const float* x     = (const float*)d_in[0];
    const float* noise = (const float*)d_in[1];
    const float* rw    = (const float*)d_in[2];
    const float* rb    = (const float*)d_in[3];
    const float* nw    = (const float*)d_in[4];
    const float* nb    = (const float*)d_in[5];
    const float* w1    = (const float*)d_in[6];
    const float* w2    = (const float*)d_in[7];
    const float* w3    = (const float*)d_in[8];
    float* out = (float*)d_out;

    cudaMemsetAsync(out, 0, (size_t)TOK * DIM * sizeof(float));
    zero_counts_kernel<<<1, 32>>>();
    router_kernel<<<TOK / 8, 256>>>(x, noise, rw, rb, nw, nb);
    scan_offsets_kernel<<<1, 32>>>();
    gather_kernel<<<NE * TOK, 256>>>(x);
    gemm1_kernel<<<dim3(HID / BN, TOK / BM, NE), 256>>>(w1, w3);
    gemm2_kernel<<<dim3(DIM / BN, TOK / BM, NE), 256>>>(w2, out);
}

// round 6
// speedup vs baseline: 2.3529x; 2.3529x over previous
#include <cuda_runtime.h>
#include <cuda_bf16.h>
#include <stdint.h>
#include <math.h>

// Problem constants
#define TOK   8192
#define DIM   1024
#define HID   2048
#define NE    8
#define NPAIR (TOK * 2)

// ---------------------------------------------------------------------------
// Device scratch
// ---------------------------------------------------------------------------
__device__ int   g_counts[NE];
__device__ int   g_offs[NE];
__device__ int   g_ptoken[NE * TOK];
__device__ float g_pgate [NE * TOK];
__device__ float g_cgate [NPAIR];
__device__ int   g_tslot [NPAIR];

__device__ __nv_bfloat16 g_w1h[(size_t)NE * HID * DIM];
__device__ __nv_bfloat16 g_w1l[(size_t)NE * HID * DIM];
__device__ __nv_bfloat16 g_w3h[(size_t)NE * HID * DIM];
__device__ __nv_bfloat16 g_w3l[(size_t)NE * HID * DIM];
__device__ __nv_bfloat16 g_w2h[(size_t)NE * DIM * HID];
__device__ __nv_bfloat16 g_w2l[(size_t)NE * DIM * HID];

__device__ __nv_bfloat16 g_Xh[(size_t)NPAIR * DIM];
__device__ __nv_bfloat16 g_Xl[(size_t)NPAIR * DIM];
__device__ __nv_bfloat16 g_Gh[(size_t)NPAIR * HID];
__device__ __nv_bfloat16 g_Gl[(size_t)NPAIR * HID];
__device__ float         g_Y [(size_t)NPAIR * DIM];

// ---------------------------------------------------------------------------
// Helpers (base ISA only: cp.async, ldmatrix, mma.sync — all legal at compute_103)
// ---------------------------------------------------------------------------
__device__ __forceinline__ uint32_t smem_u32(const void* p) {
    uint32_t a;
    asm("{ .reg .u64 t; cvta.to.shared.u64 t, %1; cvt.u32.u64 %0, t; }"
        : "=r"(a) : "l"(p));
    return a;
}

#define CP_ASYNC16(dst, src, sz) \
    asm volatile("cp.async.cg.shared.global [%0], [%1], 16, %2;" \
                 :: "r"(dst), "l"(src), "r"(sz))
#define CP_COMMIT() asm volatile("cp.async.commit_group;")
#define CP_WAIT1()  asm volatile("cp.async.wait_group 1;")
#define CP_WAIT0()  asm volatile("cp.async.wait_group 0;")

__device__ __forceinline__ void ldsm4(uint32_t* r, uint32_t addr) {
    asm volatile("ldmatrix.sync.aligned.m8n8.x4.shared.b16 {%0,%1,%2,%3}, [%4];"
                 : "=r"(r[0]), "=r"(r[1]), "=r"(r[2]), "=r"(r[3]) : "r"(addr));
}

__device__ __forceinline__ void mma16816(float* c, const uint32_t* a, const uint32_t* b) {
    asm volatile(
        "mma.sync.aligned.m16n8k16.row.col.f32.bf16.bf16.f32 "
        "{%0,%1,%2,%3}, {%4,%5,%6,%7}, {%8,%9}, {%0,%1,%2,%3};"
        : "+f"(c[0]), "+f"(c[1]), "+f"(c[2]), "+f"(c[3])
        : "r"(a[0]), "r"(a[1]), "r"(a[2]), "r"(a[3]), "r"(b[0]), "r"(b[1]));
}

__device__ __forceinline__ void split_bf16(float v, __nv_bfloat16& h, __nv_bfloat16& l) {
    h = __float2bfloat16(v);
    l = __float2bfloat16(v - __bfloat162float(h));
}

// ---------------------------------------------------------------------------
// Stage 0: zero expert counters
// ---------------------------------------------------------------------------
__global__ void zero_counts_kernel() {
    if (threadIdx.x < NE) g_counts[threadIdx.x] = 0;
}

// ---------------------------------------------------------------------------
// Weight conversion fp32 -> bf16 hi/lo
// ---------------------------------------------------------------------------
__global__ void convert_kernel(const float* __restrict__ s, int which, int n4) {
    __nv_bfloat16 *h, *l;
    if (which == 0)      { h = g_w1h; l = g_w1l; }
    else if (which == 1) { h = g_w3h; l = g_w3l; }
    else                 { h = g_w2h; l = g_w2l; }
    int i = blockIdx.x * blockDim.x + threadIdx.x;
    if (i >= n4) return;
    float4 v = ((const float4*)s)[i];
    __nv_bfloat16 hx, lx, hy, ly, hz, lz, hw, lw;
    split_bf16(v.x, hx, lx); split_bf16(v.y, hy, ly);
    split_bf16(v.z, hz, lz); split_bf16(v.w, hw, lw);
    ((__nv_bfloat162*)h)[2 * i]     = __halves2bfloat162(hx, hy);
    ((__nv_bfloat162*)h)[2 * i + 1] = __halves2bfloat162(hz, hw);
    ((__nv_bfloat162*)l)[2 * i]     = __halves2bfloat162(lx, ly);
    ((__nv_bfloat162*)l)[2 * i + 1] = __halves2bfloat162(lz, lw);
}

// ---------------------------------------------------------------------------
// Stage 1: router (noisy top-2)
// ---------------------------------------------------------------------------
__global__ void router_kernel(const float* __restrict__ x,
                              const float* __restrict__ noise,
                              const float* __restrict__ rw,
                              const float* __restrict__ rb,
                              const float* __restrict__ nw,
                              const float* __restrict__ nb)
{
    int gwarp = (int)((blockIdx.x * blockDim.x + threadIdx.x) >> 5);
    int lane  = threadIdx.x & 31;
    if (gwarp >= TOK) return;
    const float* xr = x + (size_t)gwarp * DIM;

    float accR[NE], accN[NE];
#pragma unroll
    for (int e = 0; e < NE; e++) { accR[e] = 0.0f; accN[e] = 0.0f; }
    for (int i = lane; i < DIM; i += 32) {
        float xv = xr[i];
#pragma unroll
        for (int e = 0; e < NE; e++) {
            accR[e] = fmaf(xv, rw[e * DIM + i], accR[e]);
            accN[e] = fmaf(xv, nw[e * DIM + i], accN[e]);
        }
    }
#pragma unroll
    for (int e = 0; e < NE; e++) {
#pragma unroll
        for (int o = 16; o > 0; o >>= 1) {
            accR[e] += __shfl_xor_sync(0xffffffffu, accR[e], o);
            accN[e] += __shfl_xor_sync(0xffffffffu, accN[e], o);
        }
    }
    if (lane == 0) {
        float noisy[NE];
#pragma unroll
        for (int e = 0; e < NE; e++) {
            float lg = accR[e] + rb[e];
            float nl = accN[e] + nb[e];
            float sp = fmaxf(nl, 0.0f) + log1pf(expf(-fabsf(nl)));
            noisy[e] = lg + noise[(size_t)gwarp * NE + e] * sp;
        }
        int i1 = 0;
#pragma unroll
        for (int e = 1; e < NE; e++) if (noisy[e] > noisy[i1]) i1 = e;
        int i2 = (i1 == 0) ? 1 : 0;
#pragma unroll
        for (int e = 0; e < NE; e++) {
            if (e == i1 || e == i2) continue;
            if (noisy[e] > noisy[i2]) i2 = e;
        }
        float e2 = expf(noisy[i2] - noisy[i1]);
        float inv = 1.0f / (1.0f + e2);
        int s1 = atomicAdd(&g_counts[i1], 1);
        g_ptoken[i1 * TOK + s1] = gwarp;
        g_pgate [i1 * TOK + s1] = inv;
        int s2 = atomicAdd(&g_counts[i2], 1);
        g_ptoken[i2 * TOK + s2] = gwarp;
        g_pgate [i2 * TOK + s2] = e2 * inv;
        g_tslot[2 * gwarp]     = i1 * TOK + s1;
        g_tslot[2 * gwarp + 1] = i2 * TOK + s2;
    }
}

// ---------------------------------------------------------------------------
// Stage 2: prefix scan
// ---------------------------------------------------------------------------
__global__ void scan_offsets_kernel() {
    if (threadIdx.x == 0) {
        int s = 0;
#pragma unroll
        for (int e = 0; e < NE; e++) { g_offs[e] = s; s += g_counts[e]; }
    }
}

// ---------------------------------------------------------------------------
// Stage 3: gather + bf16 hi/lo split of activations
// ---------------------------------------------------------------------------
__global__ void gather_kernel(const float* __restrict__ x) {
    int e    = blockIdx.x >> 13;
    int slot = blockIdx.x & (TOK - 1);
    if (slot >= g_counts[e]) return;
    int token = g_ptoken[e * TOK + slot];
    int p     = g_offs[e] + slot;

    float4 v = ((const float4*)(x + (size_t)token * DIM))[threadIdx.x];
    __nv_bfloat16 hx, lx, hy, ly, hz, lz, hw, lw;
    split_bf16(v.x, hx, lx); split_bf16(v.y, hy, ly);
    split_bf16(v.z, hz, lz); split_bf16(v.w, hw, lw);
    size_t o = (size_t)p * DIM + (size_t)threadIdx.x * 4;
    *(__nv_bfloat162*)&g_Xh[o]     = __halves2bfloat162(hx, hy);
    *(__nv_bfloat162*)&g_Xh[o + 2] = __halves2bfloat162(hz, hw);
    *(__nv_bfloat162*)&g_Xl[o]     = __halves2bfloat162(lx, ly);
    *(__nv_bfloat162*)&g_Xl[o + 2] = __halves2bfloat162(lz, lw);

    if (threadIdx.x == 0) g_cgate[p] = g_pgate[e * TOK + slot];
}

// ---------------------------------------------------------------------------
// GEMM tiling constants (shared by both MMA kernels)
//   smem tiles: padded rows of 40 bf16 (80 B) -> conflict-free ldmatrix
// ---------------------------------------------------------------------------
#define ROWB     80
#define A_BYTES  (128 * ROWB)   // 10240 (128-row A tile, 32 k)
#define B_BYTES  (64 * ROWB)    // 5120  (64-row  B tile, 32 k)

#define G1_STAGE (2 * A_BYTES + 4 * B_BYTES)  // 40960
#define G1_SMEM  (2 * G1_STAGE)               // 81920
#define G2_STAGE (2 * A_BYTES + 2 * B_BYTES)  // 30720
#define G2_SMEM  (2 * G2_STAGE)               // 61440

// ---------------------------------------------------------------------------
// GEMM1 (mma.sync): G = swiglu(X @ w1^T, X @ w3^T), bf16 3-term split
// block tile 128(M) x 64(N per matrix), BK=32, 8 warps (4x2), warp 32x32
// ---------------------------------------------------------------------------
__global__ void __launch_bounds__(256, 1) gemm1_mma() {
    int e   = blockIdx.z;
    int cnt = g_counts[e];
    int m0  = blockIdx.y * 128;
    if (m0 >= cnt) return;
    int base = g_offs[e];
    int n0   = blockIdx.x * 64;

    extern __shared__ char smem[];
    uint32_t sb = smem_u32(smem);
    int tid = threadIdx.x, lane = tid & 31, wid = tid >> 5;
    int wm = wid >> 1, wn = wid & 1;
    int rl = cnt - m0; if (rl > 128) rl = 128;

    const __nv_bfloat16* Ah  = g_Xh  + (size_t)(base + m0) * DIM;
    const __nv_bfloat16* Al  = g_Xl  + (size_t)(base + m0) * DIM;
    const __nv_bfloat16* B1h = g_w1h + ((size_t)e * HID + n0) * DIM;
    const __nv_bfloat16* B1l = g_w1l + ((size_t)e * HID + n0) * DIM;
    const __nv_bfloat16* B3h = g_w3h + ((size_t)e * HID + n0) * DIM;
    const __nv_bfloat16* B3l = g_w3l + ((size_t)e * HID + n0) * DIM;

    auto load_stage = [&](int ci, int buf) {
        uint32_t s = sb + buf * G1_STAGE;
        int k0 = ci * 32;
#pragma unroll
        for (int it = 0; it < 2; it++) {
            int id = it * 256 + tid;          // 0..511
            int r = id >> 2, c = id & 3;
            int sz = (r < rl) ? 16 : 0;
            size_t go = (size_t)r * DIM + k0 + c * 8;
            uint32_t so = (uint32_t)(r * ROWB + c * 16);
            CP_ASYNC16(s + so,           Ah + go, sz);
            CP_ASYNC16(s + A_BYTES + so, Al + go, sz);
        }
        {
            int r = tid >> 2, c = tid & 3;    // 64 rows x 4 chunks
            size_t go = (size_t)r * DIM + k0 + c * 8;
            uint32_t so = (uint32_t)(r * ROWB + c * 16);
            uint32_t bb = s + 2 * A_BYTES;
            CP_ASYNC16(bb + so,               B1h + go, 16);
            CP_ASYNC16(bb + B_BYTES + so,     B1l + go, 16);
            CP_ASYNC16(bb + 2 * B_BYTES + so, B3h + go, 16);
            CP_ASYNC16(bb + 3 * B_BYTES + so, B3l + go, 16);
        }
        CP_COMMIT();
    };

    float acc[2][2][4][4];
#pragma unroll
    for (int a = 0; a < 2; a++)
#pragma unroll
        for (int b = 0; b < 2; b++)
#pragma unroll
            for (int c = 0; c < 4; c++)
#pragma unroll
                for (int d = 0; d < 4; d++) acc[a][b][c][d] = 0.0f;

    // ldmatrix lane address components
    uint32_t aRow  = (uint32_t)(lane & 15);
    uint32_t aHalf = (uint32_t)((lane >> 4) * 16);
    int g = lane >> 3;
    uint32_t bRowOff = (uint32_t)((((g >> 1) * 8) + (lane & 7)) * ROWB);
    uint32_t bKOff   = (uint32_t)((g & 1) * 16);

    load_stage(0, 0);
    for (int ci = 0; ci < 32; ci++) {
        int b = ci & 1;
        if (ci + 1 < 32) { load_stage(ci + 1, b ^ 1); CP_WAIT1(); }
        else             { CP_WAIT0(); }
        __syncthreads();
        uint32_t s = sb + b * G1_STAGE;
#pragma unroll
        for (int ks = 0; ks < 2; ks++) {
            uint32_t kb = (uint32_t)(ks * 32);
            uint32_t aH[2][4], aL[2][4];
#pragma unroll
            for (int mf = 0; mf < 2; mf++) {
                uint32_t ad = s + (uint32_t)((wm * 32 + mf * 16 + aRow) * ROWB) + kb + aHalf;
                ldsm4(aH[mf], ad);
                ldsm4(aL[mf], ad + A_BYTES);
            }
            uint32_t B1H[8], B1L[8], B3H[8], B3L[8];
            uint32_t bb = s + 2 * A_BYTES;
#pragma unroll
            for (int nh = 0; nh < 2; nh++) {
                uint32_t bd = bb + (uint32_t)((wn * 32 + nh * 16) * ROWB) + bRowOff + kb + bKOff;
                ldsm4(&B1H[nh * 4], bd);
                ldsm4(&B1L[nh * 4], bd + B_BYTES);
                ldsm4(&B3H[nh * 4], bd + 2 * B_BYTES);
                ldsm4(&B3L[nh * 4], bd + 3 * B_BYTES);
            }
#pragma unroll
            for (int mf = 0; mf < 2; mf++)
#pragma unroll
                for (int nf = 0; nf < 4; nf++) {
                    mma16816(acc[0][mf][nf], aH[mf], &B1H[nf * 2]);
                    mma16816(acc[0][mf][nf], aH[mf], &B1L[nf * 2]);
                    mma16816(acc[0][mf][nf], aL[mf], &B1H[nf * 2]);
                    mma16816(acc[1][mf][nf], aH[mf], &B3H[nf * 2]);
                    mma16816(acc[1][mf][nf], aH[mf], &B3L[nf * 2]);
                    mma16816(acc[1][mf][nf], aL[mf], &B3H[nf * 2]);
                }
        }
        __syncthreads();
    }

    // Epilogue: swiglu, split, store bf16 hi/lo
#pragma unroll
    for (int mf = 0; mf < 2; mf++) {
#pragma unroll
        for (int nf = 0; nf < 4; nf++) {
            int r   = wm * 32 + mf * 16 + (lane >> 2);
            int col = n0 + wn * 32 + nf * 8 + (lane & 3) * 2;
#pragma unroll
            for (int half = 0; half < 2; half++) {
                int row = r + half * 8;
                if (row < rl) {
                    float h0 = acc[0][mf][nf][half * 2];
                    float h1 = acc[0][mf][nf][half * 2 + 1];
                    float x0 = acc[1][mf][nf][half * 2];
                    float x1 = acc[1][mf][nf][half * 2 + 1];
                    float v0 = h0 * (1.0f / (1.0f + expf(-h0))) * x0;
                    float v1 = h1 * (1.0f / (1.0f + expf(-h1))) * x1;
                    __nv_bfloat16 vh0, vl0, vh1, vl1;
                    split_bf16(v0, vh0, vl0);
                    split_bf16(v1, vh1, vl1);
                    size_t o = (size_t)(base + m0 + row) * HID + col;
                    *(__nv_bfloat162*)&g_Gh[o] = __halves2bfloat162(vh0, vh1);
                    *(__nv_bfloat162*)&g_Gl[o] = __halves2bfloat162(vl0, vl1);
                }
            }
        }
    }
}

// ---------------------------------------------------------------------------
// GEMM2 (mma.sync): Y[p] = gate[p] * (G[p] @ w2^T), bf16 3-term split
// block tile 128 x 64, BK=32, 8 warps (4x2), warp 32x32
// ---------------------------------------------------------------------------
__global__ void __launch_bounds__(256, 1) gemm2_mma() {
    int e   = blockIdx.z;
    int cnt = g_counts[e];
    int m0  = blockIdx.y * 128;
    if (m0 >= cnt) return;
    int base = g_offs[e];
    int n0   = blockIdx.x * 64;

    extern __shared__ char smem[];
    uint32_t sb = smem_u32(smem);
    int tid = threadIdx.x, lane = tid & 31, wid = tid >> 5;
    int wm = wid >> 1, wn = wid & 1;
    int rl = cnt - m0; if (rl > 128) rl = 128;

    const __nv_bfloat16* Ah = g_Gh  + (size_t)(base + m0) * HID;
    const __nv_bfloat16* Al = g_Gl  + (size_t)(base + m0) * HID;
    const __nv_bfloat16* Bh = g_w2h + ((size_t)e * DIM + n0) * HID;
    const __nv_bfloat16* Bl = g_w2l + ((size_t)e * DIM + n0) * HID;

    auto load_stage = [&](int ci, int buf) {
        uint32_t s = sb + buf * G2_STAGE;
        int k0 = ci * 32;
#pragma unroll
        for (int it = 0; it < 2; it++) {
            int id = it * 256 + tid;
            int r = id >> 2, c = id & 3;
            int sz = (r < rl) ? 16 : 0;
            size_t go = (size_t)r * HID + k0 + c * 8;
            uint32_t so = (uint32_t)(r * ROWB + c * 16);
            CP_ASYNC16(s + so,           Ah + go, sz);
            CP_ASYNC16(s + A_BYTES + so, Al + go, sz);
        }
        {
            int r = tid >> 2, c = tid & 3;
            size_t go = (size_t)r * HID + k0 + c * 8;
            uint32_t so = (uint32_t)(r * ROWB + c * 16);
            uint32_t bb = s + 2 * A_BYTES;
            CP_ASYNC16(bb + so,           Bh + go, 16);
            CP_ASYNC16(bb + B_BYTES + so, Bl + go, 16);
        }
        CP_COMMIT();
    };

    float acc[2][4][4];
#pragma unroll
    for (int a = 0; a < 2; a++)
#pragma unroll
        for (int c = 0; c < 4; c++)
#pragma unroll
            for (int d = 0; d < 4; d++) acc[a][c][d] = 0.0f;

    uint32_t aRow  = (uint32_t)(lane & 15);
    uint32_t aHalf = (uint32_t)((lane >> 4) * 16);
    int g = lane >> 3;
    uint32_t bRowOff = (uint32_t)((((g >> 1) * 8) + (lane & 7)) * ROWB);
    uint32_t bKOff   = (uint32_t)((g & 1) * 16);

    load_stage(0, 0);
    for (int ci = 0; ci < 64; ci++) {
        int b = ci & 1;
        if (ci + 1 < 64) { load_stage(ci + 1, b ^ 1); CP_WAIT1(); }
        else             { CP_WAIT0(); }
        __syncthreads();
        uint32_t s = sb + b * G2_STAGE;
#pragma unroll
        for (int ks = 0; ks < 2; ks++) {
            uint32_t kb = (uint32_t)(ks * 32);
            uint32_t aH[2][4], aL[2][4];
#pragma unroll
            for (int mf = 0; mf < 2; mf++) {
                uint32_t ad = s + (uint32_t)((wm * 32 + mf * 16 + aRow) * ROWB) + kb + aHalf;
                ldsm4(aH[mf], ad);
                ldsm4(aL[mf], ad + A_BYTES);
            }
            uint32_t BH[8], BL[8];
            uint32_t bb = s + 2 * A_BYTES;
#pragma unroll
            for (int nh = 0; nh < 2; nh++) {
                uint32_t bd = bb + (uint32_t)((wn * 32 + nh * 16) * ROWB) + bRowOff + kb + bKOff;
                ldsm4(&BH[nh * 4], bd);
                ldsm4(&BL[nh * 4], bd + B_BYTES);
            }
#pragma unroll
            for (int mf = 0; mf < 2; mf++)
#pragma unroll
                for (int nf = 0; nf < 4; nf++) {
                    mma16816(acc[mf][nf], aH[mf], &BH[nf * 2]);
                    mma16816(acc[mf][nf], aH[mf], &BL[nf * 2]);
                    mma16816(acc[mf][nf], aL[mf], &BH[nf * 2]);
                }
        }
        __syncthreads();
    }

    // Epilogue: gate-scale, store fp32 rows of Y
#pragma unroll
    for (int mf = 0; mf < 2; mf++) {
#pragma unroll
        for (int nf = 0; nf < 4; nf++) {
            int r   = wm * 32 + mf * 16 + (lane >> 2);
            int col = n0 + wn * 32 + nf * 8 + (lane & 3) * 2;
#pragma unroll
            for (int half = 0; half < 2; half++) {
                int row = r + half * 8;
                if (row < rl) {
                    float gate = g_cgate[base + m0 + row];
                    float2 v;
                    v.x = gate * acc[mf][nf][half * 2];
                    v.y = gate * acc[mf][nf][half * 2 + 1];
                    *(float2*)&g_Y[(size_t)(base + m0 + row) * DIM + col] = v;
                }
            }
        }
    }
}

// ---------------------------------------------------------------------------
// Combine: out[token] = Y[pair0] + Y[pair1]  (gates already applied)
// ---------------------------------------------------------------------------
__global__ void combine_kernel(float* __restrict__ out) {
    int t = blockIdx.x;
    int e0 = g_tslot[2 * t], e1 = g_tslot[2 * t + 1];
    int p0 = g_offs[e0 >> 13] + (e0 & (TOK - 1));
    int p1 = g_offs[e1 >> 13] + (e1 & (TOK - 1));
    float4 a = ((const float4*)(g_Y + (size_t)p0 * DIM))[threadIdx.x];
    float4 b = ((const float4*)(g_Y + (size_t)p1 * DIM))[threadIdx.x];
    float4 r = make_float4(a.x + b.x, a.y + b.y, a.z + b.z, a.w + b.w);
    ((float4*)(out + (size_t)t * DIM))[threadIdx.x] = r;
}

// ---------------------------------------------------------------------------
// Launch
// ---------------------------------------------------------------------------
extern "C" void kernel_launch(void* const* d_in, const int* in_sizes, int n_in,
                              void* d_out, int out_size)
{
    const float* x     = (const float*)d_in[0];
    const float* noise = (const float*)d_in[1];
    const float* rw    = (const float*)d_in[2];
    const float* rb    = (const float*)d_in[3];
    const float* nw    = (const float*)d_in[4];
    const float* nb    = (const float*)d_in[5];
    const float* w1    = (const float*)d_in[6];
    const float* w2    = (const float*)d_in[7];
    const float* w3    = (const float*)d_in[8];
    float* out = (float*)d_out;

    cudaFuncSetAttribute(gemm1_mma, cudaFuncAttributeMaxDynamicSharedMemorySize, G1_SMEM);
    cudaFuncSetAttribute(gemm2_mma, cudaFuncAttributeMaxDynamicSharedMemorySize, G2_SMEM);

    const int n4 = (NE * HID * DIM) / 4;

    zero_counts_kernel<<<1, 32>>>();
    convert_kernel<<<n4 / 256, 256>>>(w1, 0, n4);
    convert_kernel<<<n4 / 256, 256>>>(w3, 1, n4);
    convert_kernel<<<n4 / 256, 256>>>(w2, 2, n4);
    router_kernel<<<TOK / 8, 256>>>(x, noise, rw, rb, nw, nb);
    scan_offsets_kernel<<<1, 32>>>();
    gather_kernel<<<NE * TOK, 256>>>(x);
    gemm1_mma<<<dim3(HID / 64, TOK / 128, NE), 256, G1_SMEM>>>();
    gemm2_mma<<<dim3(DIM / 64, TOK / 128, NE), 256, G2_SMEM>>>();
    combine_kernel<<<TOK, 256>>>(out);
}

// round 7
// speedup vs baseline: 2.7017x; 1.1482x over previous
#include <cuda_runtime.h>
#include <cuda_bf16.h>
#include <stdint.h>
#include <math.h>

// Problem constants
#define TOK   8192
#define DIM   1024
#define HID   2048
#define NE    8
#define NPAIR (TOK * 2)

// ---------------------------------------------------------------------------
// Device scratch
// ---------------------------------------------------------------------------
__device__ int   g_counts[NE];
__device__ int   g_offs[NE];
__device__ int   g_ptoken[NE * TOK];
__device__ float g_pgate [NE * TOK];
__device__ float g_cgate [NPAIR];
__device__ int   g_tslot [NPAIR];

__device__ __nv_bfloat16 g_w1h[(size_t)NE * HID * DIM];
__device__ __nv_bfloat16 g_w1l[(size_t)NE * HID * DIM];
__device__ __nv_bfloat16 g_w3h[(size_t)NE * HID * DIM];
__device__ __nv_bfloat16 g_w3l[(size_t)NE * HID * DIM];
__device__ __nv_bfloat16 g_w2h[(size_t)NE * DIM * HID];
__device__ __nv_bfloat16 g_w2l[(size_t)NE * DIM * HID];

__device__ __nv_bfloat16 g_Xh[(size_t)NPAIR * DIM];
__device__ __nv_bfloat16 g_Xl[(size_t)NPAIR * DIM];
__device__ __nv_bfloat16 g_Gh[(size_t)NPAIR * HID];
__device__ __nv_bfloat16 g_Gl[(size_t)NPAIR * HID];
__device__ float         g_Y [(size_t)NPAIR * DIM];

// ---------------------------------------------------------------------------
// Helpers (base ISA only: cp.async, ldmatrix, mma.sync)
// ---------------------------------------------------------------------------
__device__ __forceinline__ uint32_t smem_u32(const void* p) {
    uint32_t a;
    asm("{ .reg .u64 t; cvta.to.shared.u64 t, %1; cvt.u32.u64 %0, t; }"
        : "=r"(a) : "l"(p));
    return a;
}

#define CP_ASYNC16(dst, src, sz) \
    asm volatile("cp.async.cg.shared.global [%0], [%1], 16, %2;" \
                 :: "r"(dst), "l"(src), "r"(sz))
#define CP_COMMIT() asm volatile("cp.async.commit_group;")
#define CP_WAIT1()  asm volatile("cp.async.wait_group 1;")
#define CP_WAIT0()  asm volatile("cp.async.wait_group 0;")

__device__ __forceinline__ void ldsm4(uint32_t* r, uint32_t addr) {
    asm volatile("ldmatrix.sync.aligned.m8n8.x4.shared.b16 {%0,%1,%2,%3}, [%4];"
                 : "=r"(r[0]), "=r"(r[1]), "=r"(r[2]), "=r"(r[3]) : "r"(addr));
}

__device__ __forceinline__ void mma16816(float* c, const uint32_t* a, const uint32_t* b) {
    asm volatile(
        "mma.sync.aligned.m16n8k16.row.col.f32.bf16.bf16.f32 "
        "{%0,%1,%2,%3}, {%4,%5,%6,%7}, {%8,%9}, {%0,%1,%2,%3};"
        : "+f"(c[0]), "+f"(c[1]), "+f"(c[2]), "+f"(c[3])
        : "r"(a[0]), "r"(a[1]), "r"(a[2]), "r"(a[3]), "r"(b[0]), "r"(b[1]));
}

__device__ __forceinline__ void split_bf16(float v, __nv_bfloat16& h, __nv_bfloat16& l) {
    h = __float2bfloat16(v);
    l = __float2bfloat16(v - __bfloat162float(h));
}

// ---------------------------------------------------------------------------
// Stage 0: zero expert counters
// ---------------------------------------------------------------------------
__global__ void zero_counts_kernel() {
    if (threadIdx.x < NE) g_counts[threadIdx.x] = 0;
}

// ---------------------------------------------------------------------------
// Weight conversion fp32 -> bf16 hi/lo (all 3 matrices in one launch)
// ---------------------------------------------------------------------------
__global__ void convert_kernel(const float* __restrict__ w1,
                               const float* __restrict__ w2,
                               const float* __restrict__ w3, int n4) {
    int blk_per = n4 / 256;
    int which = blockIdx.x / blk_per;
    int i = (blockIdx.x - which * blk_per) * 256 + threadIdx.x;
    const float* s;
    __nv_bfloat16 *h, *l;
    if (which == 0)      { s = w1; h = g_w1h; l = g_w1l; }
    else if (which == 1) { s = w3; h = g_w3h; l = g_w3l; }
    else                 { s = w2; h = g_w2h; l = g_w2l; }
    float4 v = ((const float4*)s)[i];
    __nv_bfloat16 hx, lx, hy, ly, hz, lz, hw, lw;
    split_bf16(v.x, hx, lx); split_bf16(v.y, hy, ly);
    split_bf16(v.z, hz, lz); split_bf16(v.w, hw, lw);
    ((__nv_bfloat162*)h)[2 * i]     = __halves2bfloat162(hx, hy);
    ((__nv_bfloat162*)h)[2 * i + 1] = __halves2bfloat162(hz, hw);
    ((__nv_bfloat162*)l)[2 * i]     = __halves2bfloat162(lx, ly);
    ((__nv_bfloat162*)l)[2 * i + 1] = __halves2bfloat162(lz, lw);
}

// ---------------------------------------------------------------------------
// Stage 1: router (noisy top-2)
// ---------------------------------------------------------------------------
__global__ void router_kernel(const float* __restrict__ x,
                              const float* __restrict__ noise,
                              const float* __restrict__ rw,
                              const float* __restrict__ rb,
                              const float* __restrict__ nw,
                              const float* __restrict__ nb)
{
    int gwarp = (int)((blockIdx.x * blockDim.x + threadIdx.x) >> 5);
    int lane  = threadIdx.x & 31;
    if (gwarp >= TOK) return;
    const float* xr = x + (size_t)gwarp * DIM;

    float accR[NE], accN[NE];
#pragma unroll
    for (int e = 0; e < NE; e++) { accR[e] = 0.0f; accN[e] = 0.0f; }
    for (int i = lane; i < DIM; i += 32) {
        float xv = xr[i];
#pragma unroll
        for (int e = 0; e < NE; e++) {
            accR[e] = fmaf(xv, rw[e * DIM + i], accR[e]);
            accN[e] = fmaf(xv, nw[e * DIM + i], accN[e]);
        }
    }
#pragma unroll
    for (int e = 0; e < NE; e++) {
#pragma unroll
        for (int o = 16; o > 0; o >>= 1) {
            accR[e] += __shfl_xor_sync(0xffffffffu, accR[e], o);
            accN[e] += __shfl_xor_sync(0xffffffffu, accN[e], o);
        }
    }
    if (lane == 0) {
        float noisy[NE];
#pragma unroll
        for (int e = 0; e < NE; e++) {
            float lg = accR[e] + rb[e];
            float nl = accN[e] + nb[e];
            float sp = fmaxf(nl, 0.0f) + log1pf(expf(-fabsf(nl)));
            noisy[e] = lg + noise[(size_t)gwarp * NE + e] * sp;
        }
        int i1 = 0;
#pragma unroll
        for (int e = 1; e < NE; e++) if (noisy[e] > noisy[i1]) i1 = e;
        int i2 = (i1 == 0) ? 1 : 0;
#pragma unroll
        for (int e = 0; e < NE; e++) {
            if (e == i1 || e == i2) continue;
            if (noisy[e] > noisy[i2]) i2 = e;
        }
        float e2 = expf(noisy[i2] - noisy[i1]);
        float inv = 1.0f / (1.0f + e2);
        int s1 = atomicAdd(&g_counts[i1], 1);
        g_ptoken[i1 * TOK + s1] = gwarp;
        g_pgate [i1 * TOK + s1] = inv;
        int s2 = atomicAdd(&g_counts[i2], 1);
        g_ptoken[i2 * TOK + s2] = gwarp;
        g_pgate [i2 * TOK + s2] = e2 * inv;
        g_tslot[2 * gwarp]     = i1 * TOK + s1;
        g_tslot[2 * gwarp + 1] = i2 * TOK + s2;
    }
}

// ---------------------------------------------------------------------------
// Stage 2: prefix scan
// ---------------------------------------------------------------------------
__global__ void scan_offsets_kernel() {
    if (threadIdx.x == 0) {
        int s = 0;
#pragma unroll
        for (int e = 0; e < NE; e++) { g_offs[e] = s; s += g_counts[e]; }
    }
}

// ---------------------------------------------------------------------------
// Stage 3: gather + bf16 hi/lo split of activations
// ---------------------------------------------------------------------------
__global__ void gather_kernel(const float* __restrict__ x) {
    int e    = blockIdx.x >> 13;
    int slot = blockIdx.x & (TOK - 1);
    if (slot >= g_counts[e]) return;
    int token = g_ptoken[e * TOK + slot];
    int p     = g_offs[e] + slot;

    float4 v = ((const float4*)(x + (size_t)token * DIM))[threadIdx.x];
    __nv_bfloat16 hx, lx, hy, ly, hz, lz, hw, lw;
    split_bf16(v.x, hx, lx); split_bf16(v.y, hy, ly);
    split_bf16(v.z, hz, lz); split_bf16(v.w, hw, lw);
    size_t o = (size_t)p * DIM + (size_t)threadIdx.x * 4;
    *(__nv_bfloat162*)&g_Xh[o]     = __halves2bfloat162(hx, hy);
    *(__nv_bfloat162*)&g_Xh[o + 2] = __halves2bfloat162(hz, hw);
    *(__nv_bfloat162*)&g_Xl[o]     = __halves2bfloat162(lx, ly);
    *(__nv_bfloat162*)&g_Xl[o + 2] = __halves2bfloat162(lz, lw);

    if (threadIdx.x == 0) g_cgate[p] = g_pgate[e * TOK + slot];
}

// ---------------------------------------------------------------------------
// GEMM tiling constants
// ---------------------------------------------------------------------------
#define ROWB     80
#define A_BYTES  (128 * ROWB)   // 10240
#define B_BYTES  (64 * ROWB)    // 5120

#define G1_STAGE (2 * A_BYTES + 4 * B_BYTES)  // 40960
#define G1_SMEM  (2 * G1_STAGE)               // 81920 (x2 CTAs = 160KB, fits)
#define G2_STAGE (2 * A_BYTES + 2 * B_BYTES)  // 30720
#define G2_SMEM  (2 * G2_STAGE)               // 61440 (x2 CTAs = 120KB, fits)

// ---------------------------------------------------------------------------
// GEMM1 (mma.sync): G = swiglu(X @ w1^T, X @ w3^T), bf16 3-term split
// block 128x64(per matrix), BK=32, 8 warps (4x2), warp 32x32, occupancy 2
// ---------------------------------------------------------------------------
__global__ void __launch_bounds__(256, 2) gemm1_mma() {
    int e   = blockIdx.z;
    int cnt = g_counts[e];
    int m0  = blockIdx.y * 128;
    if (m0 >= cnt) return;
    int base = g_offs[e];
    int n0   = blockIdx.x * 64;

    extern __shared__ char smem[];
    uint32_t sb = smem_u32(smem);
    int tid = threadIdx.x, lane = tid & 31, wid = tid >> 5;
    int wm = wid >> 1, wn = wid & 1;
    int rl = cnt - m0; if (rl > 128) rl = 128;

    const __nv_bfloat16* Ah  = g_Xh  + (size_t)(base + m0) * DIM;
    const __nv_bfloat16* Al  = g_Xl  + (size_t)(base + m0) * DIM;
    const __nv_bfloat16* B1h = g_w1h + ((size_t)e * HID + n0) * DIM;
    const __nv_bfloat16* B1l = g_w1l + ((size_t)e * HID + n0) * DIM;
    const __nv_bfloat16* B3h = g_w3h + ((size_t)e * HID + n0) * DIM;
    const __nv_bfloat16* B3l = g_w3l + ((size_t)e * HID + n0) * DIM;

    auto load_stage = [&](int ci, int buf) {
        uint32_t s = sb + buf * G1_STAGE;
        int k0 = ci * 32;
#pragma unroll
        for (int it = 0; it < 2; it++) {
            int id = it * 256 + tid;
            int r = id >> 2, c = id & 3;
            int sz = (r < rl) ? 16 : 0;
            size_t go = (size_t)r * DIM + k0 + c * 8;
            uint32_t so = (uint32_t)(r * ROWB + c * 16);
            CP_ASYNC16(s + so,           Ah + go, sz);
            CP_ASYNC16(s + A_BYTES + so, Al + go, sz);
        }
        {
            int r = tid >> 2, c = tid & 3;
            size_t go = (size_t)r * DIM + k0 + c * 8;
            uint32_t so = (uint32_t)(r * ROWB + c * 16);
            uint32_t bb = s + 2 * A_BYTES;
            CP_ASYNC16(bb + so,               B1h + go, 16);
            CP_ASYNC16(bb + B_BYTES + so,     B1l + go, 16);
            CP_ASYNC16(bb + 2 * B_BYTES + so, B3h + go, 16);
            CP_ASYNC16(bb + 3 * B_BYTES + so, B3l + go, 16);
        }
        CP_COMMIT();
    };

    float acc[2][2][4][4];
#pragma unroll
    for (int a = 0; a < 2; a++)
#pragma unroll
        for (int b = 0; b < 2; b++)
#pragma unroll
            for (int c = 0; c < 4; c++)
#pragma unroll
                for (int d = 0; d < 4; d++) acc[a][b][c][d] = 0.0f;

    uint32_t aRow  = (uint32_t)(lane & 15);
    uint32_t aHalf = (uint32_t)((lane >> 4) * 16);
    int g = lane >> 3;
    uint32_t bRowOff = (uint32_t)((((g >> 1) * 8) + (lane & 7)) * ROWB);
    uint32_t bKOff   = (uint32_t)((g & 1) * 16);

    load_stage(0, 0);
    for (int ci = 0; ci < 32; ci++) {
        int b = ci & 1;
        if (ci + 1 < 32) { load_stage(ci + 1, b ^ 1); CP_WAIT1(); }
        else             { CP_WAIT0(); }
        __syncthreads();
        uint32_t s = sb + b * G1_STAGE;
#pragma unroll
        for (int ks = 0; ks < 2; ks++) {
            uint32_t kb = (uint32_t)(ks * 32);
            uint32_t aH[2][4], aL[2][4];
#pragma unroll
            for (int mf = 0; mf < 2; mf++) {
                uint32_t ad = s + (uint32_t)((wm * 32 + mf * 16 + aRow) * ROWB) + kb + aHalf;
                ldsm4(aH[mf], ad);
                ldsm4(aL[mf], ad + A_BYTES);
            }
            uint32_t bb = s + 2 * A_BYTES;
#pragma unroll
            for (int nh = 0; nh < 2; nh++) {
                // Load only this nh's B fragments (16 regs live, not 32)
                uint32_t bd = bb + (uint32_t)((wn * 32 + nh * 16) * ROWB) + bRowOff + kb + bKOff;
                uint32_t b1h[4], b1l[4], b3h[4], b3l[4];
                ldsm4(b1h, bd);
                ldsm4(b1l, bd + B_BYTES);
                ldsm4(b3h, bd + 2 * B_BYTES);
                ldsm4(b3l, bd + 3 * B_BYTES);
#pragma unroll
                for (int mf = 0; mf < 2; mf++)
#pragma unroll
                    for (int j = 0; j < 2; j++) {
                        int nf = nh * 2 + j;
                        mma16816(acc[0][mf][nf], aH[mf], &b1h[j * 2]);
                        mma16816(acc[0][mf][nf], aH[mf], &b1l[j * 2]);
                        mma16816(acc[0][mf][nf], aL[mf], &b1h[j * 2]);
                        mma16816(acc[1][mf][nf], aH[mf], &b3h[j * 2]);
                        mma16816(acc[1][mf][nf], aH[mf], &b3l[j * 2]);
                        mma16816(acc[1][mf][nf], aL[mf], &b3h[j * 2]);
                    }
            }
        }
        __syncthreads();
    }

    // Epilogue: swiglu, split, store bf16 hi/lo
#pragma unroll
    for (int mf = 0; mf < 2; mf++) {
#pragma unroll
        for (int nf = 0; nf < 4; nf++) {
            int r   = wm * 32 + mf * 16 + (lane >> 2);
            int col = n0 + wn * 32 + nf * 8 + (lane & 3) * 2;
#pragma unroll
            for (int half = 0; half < 2; half++) {
                int row = r + half * 8;
                if (row < rl) {
                    float h0 = acc[0][mf][nf][half * 2];
                    float h1 = acc[0][mf][nf][half * 2 + 1];
                    float x0 = acc[1][mf][nf][half * 2];
                    float x1 = acc[1][mf][nf][half * 2 + 1];
                    float v0 = h0 * (1.0f / (1.0f + __expf(-h0))) * x0;
                    float v1 = h1 * (1.0f / (1.0f + __expf(-h1))) * x1;
                    __nv_bfloat16 vh0, vl0, vh1, vl1;
                    split_bf16(v0, vh0, vl0);
                    split_bf16(v1, vh1, vl1);
                    size_t o = (size_t)(base + m0 + row) * HID + col;
                    *(__nv_bfloat162*)&g_Gh[o] = __halves2bfloat162(vh0, vh1);
                    *(__nv_bfloat162*)&g_Gl[o] = __halves2bfloat162(vl0, vl1);
                }
            }
        }
    }
}

// ---------------------------------------------------------------------------
// GEMM2 (mma.sync): Y[p] = gate[p] * (G[p] @ w2^T), bf16 3-term split
// ---------------------------------------------------------------------------
__global__ void __launch_bounds__(256, 2) gemm2_mma() {
    int e   = blockIdx.z;
    int cnt = g_counts[e];
    int m0  = blockIdx.y * 128;
    if (m0 >= cnt) return;
    int base = g_offs[e];
    int n0   = blockIdx.x * 64;

    extern __shared__ char smem[];
    uint32_t sb = smem_u32(smem);
    int tid = threadIdx.x, lane = tid & 31, wid = tid >> 5;
    int wm = wid >> 1, wn = wid & 1;
    int rl = cnt - m0; if (rl > 128) rl = 128;

    const __nv_bfloat16* Ah = g_Gh  + (size_t)(base + m0) * HID;
    const __nv_bfloat16* Al = g_Gl  + (size_t)(base + m0) * HID;
    const __nv_bfloat16* Bh = g_w2h + ((size_t)e * DIM + n0) * HID;
    const __nv_bfloat16* Bl = g_w2l + ((size_t)e * DIM + n0) * HID;

    auto load_stage = [&](int ci, int buf) {
        uint32_t s = sb + buf * G2_STAGE;
        int k0 = ci * 32;
#pragma unroll
        for (int it = 0; it < 2; it++) {
            int id = it * 256 + tid;
            int r = id >> 2, c = id & 3;
            int sz = (r < rl) ? 16 : 0;
            size_t go = (size_t)r * HID + k0 + c * 8;
            uint32_t so = (uint32_t)(r * ROWB + c * 16);
            CP_ASYNC16(s + so,           Ah + go, sz);
            CP_ASYNC16(s + A_BYTES + so, Al + go, sz);
        }
        {
            int r = tid >> 2, c = tid & 3;
            size_t go = (size_t)r * HID + k0 + c * 8;
            uint32_t so = (uint32_t)(r * ROWB + c * 16);
            uint32_t bb = s + 2 * A_BYTES;
            CP_ASYNC16(bb + so,           Bh + go, 16);
            CP_ASYNC16(bb + B_BYTES + so, Bl + go, 16);
        }
        CP_COMMIT();
    };

    float acc[2][4][4];
#pragma unroll
    for (int a = 0; a < 2; a++)
#pragma unroll
        for (int c = 0; c < 4; c++)
#pragma unroll
            for (int d = 0; d < 4; d++) acc[a][c][d] = 0.0f;

    uint32_t aRow  = (uint32_t)(lane & 15);
    uint32_t aHalf = (uint32_t)((lane >> 4) * 16);
    int g = lane >> 3;
    uint32_t bRowOff = (uint32_t)((((g >> 1) * 8) + (lane & 7)) * ROWB);
    uint32_t bKOff   = (uint32_t)((g & 1) * 16);

    load_stage(0, 0);
    for (int ci = 0; ci < 64; ci++) {
        int b = ci & 1;
        if (ci + 1 < 64) { load_stage(ci + 1, b ^ 1); CP_WAIT1(); }
        else             { CP_WAIT0(); }
        __syncthreads();
        uint32_t s = sb + b * G2_STAGE;
#pragma unroll
        for (int ks = 0; ks < 2; ks++) {
            uint32_t kb = (uint32_t)(ks * 32);
            uint32_t aH[2][4], aL[2][4];
#pragma unroll
            for (int mf = 0; mf < 2; mf++) {
                uint32_t ad = s + (uint32_t)((wm * 32 + mf * 16 + aRow) * ROWB) + kb + aHalf;
                ldsm4(aH[mf], ad);
                ldsm4(aL[mf], ad + A_BYTES);
            }
            uint32_t bb = s + 2 * A_BYTES;
#pragma unroll
            for (int nh = 0; nh < 2; nh++) {
                uint32_t bd = bb + (uint32_t)((wn * 32 + nh * 16) * ROWB) + bRowOff + kb + bKOff;
                uint32_t bh[4], bl[4];
                ldsm4(bh, bd);
                ldsm4(bl, bd + B_BYTES);
#pragma unroll
                for (int mf = 0; mf < 2; mf++)
#pragma unroll
                    for (int j = 0; j < 2; j++) {
                        int nf = nh * 2 + j;
                        mma16816(acc[mf][nf], aH[mf], &bh[j * 2]);
                        mma16816(acc[mf][nf], aH[mf], &bl[j * 2]);
                        mma16816(acc[mf][nf], aL[mf], &bh[j * 2]);
                    }
            }
        }
        __syncthreads();
    }

    // Epilogue: gate-scale, store fp32 rows of Y
#pragma unroll
    for (int mf = 0; mf < 2; mf++) {
#pragma unroll
        for (int nf = 0; nf < 4; nf++) {
            int r   = wm * 32 + mf * 16 + (lane >> 2);
            int col = n0 + wn * 32 + nf * 8 + (lane & 3) * 2;
#pragma unroll
            for (int half = 0; half < 2; half++) {
                int row = r + half * 8;
                if (row < rl) {
                    float gate = g_cgate[base + m0 + row];
                    float2 v;
                    v.x = gate * acc[mf][nf][half * 2];
                    v.y = gate * acc[mf][nf][half * 2 + 1];
                    *(float2*)&g_Y[(size_t)(base + m0 + row) * DIM + col] = v;
                }
            }
        }
    }
}

// ---------------------------------------------------------------------------
// Combine: out[token] = Y[pair0] + Y[pair1]
// ---------------------------------------------------------------------------
__global__ void combine_kernel(float* __restrict__ out) {
    int t = blockIdx.x;
    int e0 = g_tslot[2 * t], e1 = g_tslot[2 * t + 1];
    int p0 = g_offs[e0 >> 13] + (e0 & (TOK - 1));
    int p1 = g_offs[e1 >> 13] + (e1 & (TOK - 1));
    float4 a = ((const float4*)(g_Y + (size_t)p0 * DIM))[threadIdx.x];
    float4 b = ((const float4*)(g_Y + (size_t)p1 * DIM))[threadIdx.x];
    float4 r = make_float4(a.x + b.x, a.y + b.y, a.z + b.z, a.w + b.w);
    ((float4*)(out + (size_t)t * DIM))[threadIdx.x] = r;
}

// ---------------------------------------------------------------------------
// Launch
// ---------------------------------------------------------------------------
extern "C" void kernel_launch(void* const* d_in, const int* in_sizes, int n_in,
                              void* d_out, int out_size)
{
    const float* x     = (const float*)d_in[0];
    const float* noise = (const float*)d_in[1];
    const float* rw    = (const float*)d_in[2];
    const float* rb    = (const float*)d_in[3];
    const float* nw    = (const float*)d_in[4];
    const float* nb    = (const float*)d_in[5];
    const float* w1    = (const float*)d_in[6];
    const float* w2    = (const float*)d_in[7];
    const float* w3    = (const float*)d_in[8];
    float* out = (float*)d_out;

    cudaFuncSetAttribute(gemm1_mma, cudaFuncAttributeMaxDynamicSharedMemorySize, G1_SMEM);
    cudaFuncSetAttribute(gemm2_mma, cudaFuncAttributeMaxDynamicSharedMemorySize, G2_SMEM);

    const int n4 = (NE * HID * DIM) / 4;

    zero_counts_kernel<<<1, 32>>>();
    convert_kernel<<<3 * (n4 / 256), 256>>>(w1, w2, w3, n4);
    router_kernel<<<TOK / 8, 256>>>(x, noise, rw, rb, nw, nb);
    scan_offsets_kernel<<<1, 32>>>();
    gather_kernel<<<NE * TOK, 256>>>(x);
    gemm1_mma<<<dim3(HID / 64, TOK / 128, NE), 256, G1_SMEM>>>();
    gemm2_mma<<<dim3(DIM / 64, TOK / 128, NE), 256, G2_SMEM>>>();
    combine_kernel<<<TOK, 256>>>(out);
}